// round 16
// baseline (speedup 1.0000x reference)
#include <cuda_runtime.h>
#include <cstdint>

#define Bsz 64
#define Tsz 4096
#define Dsz 128
#define Hsz 256

// ---------------- packed fp32x2 helpers (sm_103a) ----------------
__device__ __forceinline__ unsigned long long pack2(float a, float b) {
    unsigned long long r;
    asm("mov.b64 %0, {%1, %2};" : "=l"(r) : "f"(a), "f"(b));
    return r;
}
__device__ __forceinline__ void fma2(unsigned long long& d, unsigned long long a, unsigned long long b) {
    asm("fma.rn.f32x2 %0, %1, %2, %0;" : "+l"(d) : "l"(a), "l"(b));
}
__device__ __forceinline__ float2 unpack2(unsigned long long p) {
    float2 v;
    asm("mov.b64 {%0, %1}, %2;" : "=f"(v.x), "=f"(v.y) : "l"(p));
    return v;
}

__device__ __forceinline__ void mbar_wait_parity(unsigned addr, unsigned phase) {
    asm volatile(
        "{\n"
        ".reg .pred P%=;\n"
        "LW%=:\n"
        "mbarrier.try_wait.parity.acquire.cluster.shared::cta.b64 P%=, [%0], %1, 0x989680;\n"
        "@P%= bra LD%=;\n"
        "bra LW%=;\n"
        "LD%=:\n"
        "}\n"
        :: "r"(addr), "r"(phase) : "memory");
}

// fast tanh: 1 - 2/(e^{2x}+1). Validated R8-R15: rel_err ~2.5-3.3e-7.
__device__ __forceinline__ float tanh_fast(float s) {
    float e;
    asm("ex2.approx.f32 %0, %1;" : "=f"(e) : "f"(s * 2.8853900817779268f));
    float r;
    asm("rcp.approx.f32 %0, %1;" : "=f"(r) : "f"(e + 1.0f));
    return __fmaf_rn(-2.0f, r, 1.0f);
}

// =====================================================================
// Single fused kernel (R11 base, overheads excised):
//   64 clusters x 2 CTAs, 512 threads/CTA, 16 warps.
//   Warp w owns cols cg = rank*128 + w*8 + c via XOR slot map
//   (slot j = col j^m, m=(lane>>2)&7) -> select-free butterfly.
//   Lane: h slivers  kl = rank*128+4*lane (local), kr = kl^128 (remote);
//         x sliver   lx = 4*lane.
//   x staged in an 8-row smem ring; 2KB bulk per 4 steps (tid32).
//   Ring wait shifted ONE GROUP EARLY (at group g wait for g+1's rows),
//   so ALL x-MACs issue pre-barrier. Warp0 waits the h-mbar, warp1 the
//   x-mbar — in parallel, both released by the same BAR.
//   h exchange identical to R6/R11: warp0 mbar wait, 512B bulk (tid0).
// =====================================================================
__global__ void __cluster_dims__(2, 1, 1) __launch_bounds__(512, 1)
rnn_fused_kernel(const float* __restrict__ x,
                 const float* __restrict__ Wx,
                 const float* __restrict__ bx,
                 const float* __restrict__ Wh,
                 const float* __restrict__ bh,
                 float* __restrict__ out)
{
    __shared__ __align__(16) float hbuf[2][Hsz];           // 2KB
    __shared__ __align__(512) float xring[8 * Dsz];        // 4KB, row t at slot t&7
    __shared__ __align__(8) unsigned long long mbar[2];    // h exchange
    __shared__ __align__(8) unsigned long long xmbar[2];   // x prefetch

    const int tid  = threadIdx.x;
    const int lane = tid & 31;
    const int warp = tid >> 5;

    unsigned rank;
    asm("mov.u32 %0, %%cluster_ctarank;" : "=r"(rank));
    const int b = blockIdx.x >> 1;

    const int loc_base = (int)rank * 128;
    const int kl = loc_base + 4 * lane;        // local h k sliver
    const int kr = kl ^ 128;                   // remote h k sliver
    const int lx = 4 * lane;                   // x-dim sliver
    const int cg_base = loc_base + warp * 8;   // warp's first column

    const int m = (lane >> 2) & 7;             // column-slot XOR key
    const int cg_f = cg_base + m;              // this lane's final column
    const bool fin = ((lane & 3) == 0);

    // Register-resident weights: slot c covers column cg_base + (c ^ m)
    unsigned long long wl[8][2], wr[8][2], wx[8][2];
#pragma unroll
    for (int c = 0; c < 8; ++c) {
        const int cg = cg_base + (c ^ m);
        wl[c][0] = pack2(__ldg(&Wh[(size_t)(kl + 0) * Hsz + cg]),
                         __ldg(&Wh[(size_t)(kl + 1) * Hsz + cg]));
        wl[c][1] = pack2(__ldg(&Wh[(size_t)(kl + 2) * Hsz + cg]),
                         __ldg(&Wh[(size_t)(kl + 3) * Hsz + cg]));
        wr[c][0] = pack2(__ldg(&Wh[(size_t)(kr + 0) * Hsz + cg]),
                         __ldg(&Wh[(size_t)(kr + 1) * Hsz + cg]));
        wr[c][1] = pack2(__ldg(&Wh[(size_t)(kr + 2) * Hsz + cg]),
                         __ldg(&Wh[(size_t)(kr + 3) * Hsz + cg]));
        wx[c][0] = pack2(__ldg(&Wx[(size_t)(lx + 0) * Hsz + cg]),
                         __ldg(&Wx[(size_t)(lx + 1) * Hsz + cg]));
        wx[c][1] = pack2(__ldg(&Wx[(size_t)(lx + 2) * Hsz + cg]),
                         __ldg(&Wx[(size_t)(lx + 3) * Hsz + cg]));
    }

    const float bias = fin ? (__ldg(&bx[cg_f]) + __ldg(&bh[cg_f])) : 0.0f;

    // h0 = 0 both buffers; preload x rows 0..7 (groups 0 and 1)
    for (int i = tid; i < 2 * Hsz; i += 512) ((float*)hbuf)[i] = 0.0f;
    const float* xb = x + (size_t)b * Tsz * Dsz;
    for (int i = tid; i < 8 * Dsz; i += 512) xring[i] = __ldg(&xb[i]);

    const unsigned hb_s   = (unsigned)__cvta_generic_to_shared(hbuf);
    const unsigned bar_s  = (unsigned)__cvta_generic_to_shared(mbar);
    const unsigned xbar_s = (unsigned)__cvta_generic_to_shared(xmbar);
    const unsigned xr_s   = (unsigned)__cvta_generic_to_shared(xring);
    if (tid == 0) {
        asm volatile("mbarrier.init.shared.b64 [%0], 1;" :: "r"(bar_s) : "memory");
        asm volatile("mbarrier.init.shared.b64 [%0], 1;" :: "r"(bar_s + 8) : "memory");
        asm volatile("mbarrier.init.shared.b64 [%0], 1;" :: "r"(xbar_s) : "memory");
        asm volatile("mbarrier.init.shared.b64 [%0], 1;" :: "r"(xbar_s + 8) : "memory");
        asm volatile("mbarrier.arrive.expect_tx.shared.b64 _, [%0], 512;" :: "r"(bar_s) : "memory");
        asm volatile("mbarrier.arrive.expect_tx.shared.b64 _, [%0], 512;" :: "r"(bar_s + 8) : "memory");
        asm volatile("mbarrier.arrive.expect_tx.shared.b64 _, [%0], 2048;" :: "r"(xbar_s) : "memory");
        asm volatile("mbarrier.arrive.expect_tx.shared.b64 _, [%0], 2048;" :: "r"(xbar_s + 8) : "memory");
    }
    __syncthreads();
    asm volatile("barrier.cluster.arrive.aligned;" ::: "memory");
    asm volatile("barrier.cluster.wait.aligned;" ::: "memory");

    const unsigned peer = rank ^ 1u;
    unsigned hb_peer, bar_peer;
    asm("mapa.shared::cluster.u32 %0, %1, %2;" : "=r"(hb_peer)  : "r"(hb_s),  "r"(peer));
    asm("mapa.shared::cluster.u32 %0, %1, %2;" : "=r"(bar_peer) : "r"(bar_s), "r"(peer));

    const size_t obase = ((size_t)b * Tsz) * Hsz + cg_f;

    unsigned ph0 = 0, ph1 = 0;

    for (int t0 = 0; t0 < Tsz; t0 += 4) {
        const int g = t0 >> 2;
#pragma unroll
        for (int u = 0; u < 4; ++u) {
            const int t  = t0 + u;
            const int p  = u & 1;
            const int np = p ^ 1;

            unsigned long long acc[8];
#pragma unroll
            for (int c = 0; c < 8; ++c) acc[c] = 0ULL;

            // x-MAC — ALWAYS pre-barrier: this group's rows were waited
            // for at the previous group (early wait), or preloaded (g<2).
            {
                ulonglong2 xv = *(const ulonglong2*)&xring[(t & 7) * Dsz + lx];
#pragma unroll
                for (int c = 0; c < 8; ++c) {
                    fma2(acc[c], xv.x, wx[c][0]);
                    fma2(acc[c], xv.y, wx[c][1]);
                }
            }

            // local-half h MAC — hides the peer bulk still in flight
            {
                ulonglong2 hv = *(const ulonglong2*)&hbuf[p][kl];
#pragma unroll
                for (int c = 0; c < 8; ++c) {
                    fma2(acc[c], hv.x, wl[c][0]);
                    fma2(acc[c], hv.y, wl[c][1]);
                }
            }

            // PARALLEL waiters: warp0 polls the h mbar, warp1 polls the
            // x mbar (one group early). Everyone else parks on bar.sync.
            if (warp == 0) {
                if (t > 0) {
                    const unsigned bs = bar_s + (unsigned)p * 8u;
                    if (p) { mbar_wait_parity(bs, ph1); ph1 ^= 1u; }
                    else   { mbar_wait_parity(bs, ph0); ph0 ^= 1u; }
                    if (tid == 0)
                        asm volatile("mbarrier.arrive.expect_tx.shared.b64 _, [%0], 512;"
                                     :: "r"(bs) : "memory");
                }
            } else if (warp == 1 && u == 0) {
                const int a = g + 1;               // group whose rows we await
                if (a >= 2 && a * 4 < Tsz) {
                    const unsigned xs_ = xbar_s + (unsigned)(a & 1) * 8u;
                    mbar_wait_parity(xs_, (unsigned)(((a >> 1) + 1) & 1));
                    if (tid == 32)
                        asm volatile("mbarrier.arrive.expect_tx.shared.b64 _, [%0], 2048;"
                                     :: "r"(xs_) : "memory");
                }
            }
            __syncthreads();   // peer h half + next group's ring rows visible

            // remote-half h MAC
            {
                ulonglong2 hv = *(const ulonglong2*)&hbuf[p][kr];
#pragma unroll
                for (int c = 0; c < 8; ++c) {
                    fma2(acc[c], hv.x, wr[c][0]);
                    fma2(acc[c], hv.y, wr[c][1]);
                }
            }

            // scalarize: s[j] = partial for column cg_base + (j ^ m)
            float s[8];
#pragma unroll
            for (int c = 0; c < 8; ++c) {
                float2 v = unpack2(acc[c]);
                s[c] = v.x + v.y;
            }

            // select-free butterfly (col(slot j) = j ^ m)
            float t4[4];
#pragma unroll
            for (int j = 0; j < 4; ++j)
                t4[j] = s[j] + __shfl_xor_sync(0xFFFFFFFFu, s[j + 4], 16);
            float t2[2];
#pragma unroll
            for (int j = 0; j < 2; ++j)
                t2[j] = t4[j] + __shfl_xor_sync(0xFFFFFFFFu, t4[j + 2], 8);
            float sum = t2[0] + __shfl_xor_sync(0xFFFFFFFFu, t2[1], 4);
            sum += __shfl_xor_sync(0xFFFFFFFFu, sum, 2);
            sum += __shfl_xor_sync(0xFFFFFFFFu, sum, 1);

            float hn = 0.0f;
            if (fin) {
                hn = tanh_fast(sum + bias);
                hbuf[np][cg_f] = hn;               // own half of h(t+1)
            }
            __syncthreads();   // STS visible; all ring/hbuf reads done

            if (tid == 0 && t + 1 < Tsz) {
                asm volatile("fence.proxy.async.shared::cta;" ::: "memory");
                const unsigned off = (unsigned)np * 1024u + (unsigned)rank * 512u;
                asm volatile(
                    "cp.async.bulk.shared::cluster.shared::cta.mbarrier::complete_tx::bytes "
                    "[%0], [%1], %2, [%3];"
                    :: "r"(hb_peer + off), "r"(hb_s + off), "r"(512u),
                       "r"(bar_peer + (unsigned)np * 8u)
                    : "memory");
            }
            // x prefetch (tid32): rows t0+8..t0+11 (group g+2) into the
            // half that group g just finished reading.
            if (tid == 32 && u == 3 && t0 + 8 < Tsz) {
                asm volatile("fence.proxy.async.shared::cta;" ::: "memory");
                const unsigned xoff = (unsigned)(t0 & 7) * (Dsz * 4u);
                const unsigned xmb  = xbar_s + (unsigned)(g & 1) * 8u;
                asm volatile(
                    "cp.async.bulk.shared::cluster.global.mbarrier::complete_tx::bytes "
                    "[%0], [%1], %2, [%3];"
                    :: "r"(xr_s + xoff),
                       "l"(xb + (size_t)(t0 + 8) * Dsz),
                       "r"(2048u), "r"(xmb)
                    : "memory");
            }

            // off-chain output write
            if (fin) out[obase + (size_t)t * Hsz] = hn;
        }
    }

    asm volatile("barrier.cluster.arrive.aligned;" ::: "memory");
    asm volatile("barrier.cluster.wait.aligned;" ::: "memory");
}

// =====================================================================
extern "C" void kernel_launch(void* const* d_in, const int* in_sizes, int n_in,
                              void* d_out, int out_size)
{
    const float* x  = (const float*)d_in[0];  // [64, 4096, 128]
    const float* Wx = (const float*)d_in[1];  // [128, 256]
    const float* bx = (const float*)d_in[2];  // [256]
    const float* Wh = (const float*)d_in[3];  // [256, 256]
    const float* bh = (const float*)d_in[4];  // [256]
    float* out = (float*)d_out;               // [64, 4096, 256]

    rnn_fused_kernel<<<2 * Bsz, 512>>>(x, Wx, bx, Wh, bh, out);
}

// round 17
// speedup vs baseline: 1.1812x; 1.1812x over previous
#include <cuda_runtime.h>
#include <cstdint>
#include <math.h>

#define Bsz 64
#define Tsz 4096
#define Dsz 128
#define Hsz 256

// Scratch for the input projection xp = x @ Wx + bx : [B][T][H] fp32
__device__ float g_xp[(size_t)Bsz * Tsz * Hsz];

// ---------------- packed fp32x2 helpers (sm_103a) ----------------
__device__ __forceinline__ unsigned long long pack2(float a, float b) {
    unsigned long long r;
    asm("mov.b64 %0, {%1, %2};" : "=l"(r) : "f"(a), "f"(b));
    return r;
}
__device__ __forceinline__ void fma2(unsigned long long& d, unsigned long long a, unsigned long long b) {
    asm("fma.rn.f32x2 %0, %1, %2, %0;" : "+l"(d) : "l"(a), "l"(b));
}
__device__ __forceinline__ float2 unpack2(unsigned long long p) {
    float2 v;
    asm("mov.b64 {%0, %1}, %2;" : "=f"(v.x), "=f"(v.y) : "l"(p));
    return v;
}

__device__ __forceinline__ void mbar_wait_parity(unsigned addr, unsigned phase) {
    asm volatile(
        "{\n"
        ".reg .pred P%=;\n"
        "LW%=:\n"
        "mbarrier.try_wait.parity.acquire.cluster.shared::cta.b64 P%=, [%0], %1, 0x989680;\n"
        "@P%= bra LD%=;\n"
        "bra LW%=;\n"
        "LD%=:\n"
        "}\n"
        :: "r"(addr), "r"(phase) : "memory");
}

// fast tanh: 1 - 2/(e^{2x}+1). MUFU EX2 + RCP, ~1e-6 rel error.
__device__ __forceinline__ float tanh_fast(float x) {
    float e = __expf(2.0f * x);
    return 1.0f - __fdividef(2.0f, e + 1.0f);
}

// =====================================================================
// Kernel 1: xp = x @ Wx + bx
// =====================================================================
__global__ void __launch_bounds__(256, 2) xp_gemm_kernel(
    const float* __restrict__ x,
    const float* __restrict__ Wx,
    const float* __restrict__ bx)
{
    extern __shared__ float sm[];
    float* xs = sm;               // [128][128], k-major
    float* ws = sm + 128 * 128;   // [128][64]

    const int tid = threadIdx.x;
    const size_t row0 = (size_t)blockIdx.x * 128;
    const int n_off = blockIdx.y * 64;

    {
        const int row = tid & 127;
        const int kh  = (tid >> 7) * 64;
        const float4* src = (const float4*)(x + (row0 + row) * Dsz + kh);
#pragma unroll
        for (int i = 0; i < 16; ++i) {
            float4 v = src[i];
            int k = kh + i * 4;
            xs[(k + 0) * 128 + row] = v.x;
            xs[(k + 1) * 128 + row] = v.y;
            xs[(k + 2) * 128 + row] = v.z;
            xs[(k + 3) * 128 + row] = v.w;
        }
    }
    {
        const int k = tid >> 1;
        const int half = (tid & 1) * 32;
        const float4* src = (const float4*)(Wx + (size_t)k * Hsz + n_off + half);
        float4* dst = (float4*)(ws + k * 64 + half);
#pragma unroll
        for (int i = 0; i < 8; ++i) dst[i] = src[i];
    }
    __syncthreads();

    const int im = tid >> 4, in = tid & 15;
    const int m0 = im * 8, n0 = in * 4;

    unsigned long long acc[4][4];
#pragma unroll
    for (int i = 0; i < 4; ++i)
#pragma unroll
        for (int j = 0; j < 4; ++j) acc[i][j] = 0ULL;

#pragma unroll 8
    for (int k = 0; k < 128; ++k) {
        const ulonglong2* ap = (const ulonglong2*)(xs + k * 128 + m0);
        ulonglong2 av0 = ap[0];
        ulonglong2 av1 = ap[1];
        unsigned long long a[4] = {av0.x, av0.y, av1.x, av1.y};
        float4 bv = *(const float4*)(ws + k * 64 + n0);
        unsigned long long bd[4];
        bd[0] = pack2(bv.x, bv.x);
        bd[1] = pack2(bv.y, bv.y);
        bd[2] = pack2(bv.z, bv.z);
        bd[3] = pack2(bv.w, bv.w);
#pragma unroll
        for (int i = 0; i < 4; ++i)
#pragma unroll
            for (int j = 0; j < 4; ++j)
                fma2(acc[i][j], a[i], bd[j]);
    }

    float bxv[4];
#pragma unroll
    for (int j = 0; j < 4; ++j) bxv[j] = __ldg(&bx[n_off + n0 + j]);

#pragma unroll
    for (int i = 0; i < 4; ++i) {
        float4 o0, o1;
        float2 c0 = unpack2(acc[i][0]); o0.x = c0.x + bxv[0]; o1.x = c0.y + bxv[0];
        float2 c1 = unpack2(acc[i][1]); o0.y = c1.x + bxv[1]; o1.y = c1.y + bxv[1];
        float2 c2 = unpack2(acc[i][2]); o0.z = c2.x + bxv[2]; o1.z = c2.y + bxv[2];
        float2 c3 = unpack2(acc[i][3]); o0.w = c3.x + bxv[3]; o1.w = c3.y + bxv[3];
        size_t r0 = row0 + m0 + 2 * i;
        *(float4*)(g_xp + r0 * Hsz + n_off + n0)       = o0;
        *(float4*)(g_xp + (r0 + 1) * Hsz + n_off + n0) = o1;
    }
}

// =====================================================================
// Kernel 2: recurrence.
//   64 clusters x 2 CTAs, 512 threads/CTA, 16 warps.
//   Warp w owns cols cg = rank*128 + w*8 + c; lane's slot j maps to
//   column j ^ m (m = (lane>>2)&7) -> SELECT-FREE butterfly reduce.
//   Lane l's k slivers: local kl = rank*128+4l, remote kr = kl^128.
//   Per step: local MAC -> [warp0 only: mbar wait] -> bar.sync ->
//   remote MAC -> 9-shfl select-free reduce -> finalizers tanh+STS+STG
//   -> bar.sync -> tid0 one 512B bulk to peer (single complete_tx).
// =====================================================================
__global__ void __cluster_dims__(2, 1, 1) __launch_bounds__(512, 1)
rnn_kernel(const float* __restrict__ Wh,
           const float* __restrict__ bh,
           float* __restrict__ out)
{
    __shared__ __align__(16) float hbuf[2][Hsz];   // [buf][global k]
    __shared__ __align__(8) unsigned long long mbar[2];

    const int tid  = threadIdx.x;
    const int lane = tid & 31;
    const int warp = tid >> 5;

    unsigned rank;
    asm("mov.u32 %0, %%cluster_ctarank;" : "=r"(rank));
    const int b = blockIdx.x >> 1;

    const int loc_base = (int)rank * 128;
    const int kl = loc_base + 4 * lane;        // local k sliver
    const int kr = kl ^ 128;                   // remote k sliver
    const int cg_base = loc_base + warp * 8;   // warp's first column

    const int m = (lane >> 2) & 7;             // column-slot XOR key
    const int cg_f = cg_base + m;              // this lane's final column
    const bool fin = ((lane & 3) == 0);

    // Register-resident Wh: slot c covers column cg_base + (c ^ m)
    unsigned long long wl[8][2], wr[8][2];
#pragma unroll
    for (int c = 0; c < 8; ++c) {
        const int cg = cg_base + (c ^ m);
        wl[c][0] = pack2(__ldg(&Wh[(size_t)(kl + 0) * Hsz + cg]),
                         __ldg(&Wh[(size_t)(kl + 1) * Hsz + cg]));
        wl[c][1] = pack2(__ldg(&Wh[(size_t)(kl + 2) * Hsz + cg]),
                         __ldg(&Wh[(size_t)(kl + 3) * Hsz + cg]));
        wr[c][0] = pack2(__ldg(&Wh[(size_t)(kr + 0) * Hsz + cg]),
                         __ldg(&Wh[(size_t)(kr + 1) * Hsz + cg]));
        wr[c][1] = pack2(__ldg(&Wh[(size_t)(kr + 2) * Hsz + cg]),
                         __ldg(&Wh[(size_t)(kr + 3) * Hsz + cg]));
    }

    // h0 = 0 in both buffers; init + pre-arm both barriers (512B each)
    for (int i = tid; i < 2 * Hsz; i += 512) ((float*)hbuf)[i] = 0.0f;
    const unsigned hb_s  = (unsigned)__cvta_generic_to_shared(hbuf);
    const unsigned bar_s = (unsigned)__cvta_generic_to_shared(mbar);
    if (tid == 0) {
        asm volatile("mbarrier.init.shared.b64 [%0], 1;" :: "r"(bar_s) : "memory");
        asm volatile("mbarrier.init.shared.b64 [%0], 1;" :: "r"(bar_s + 8) : "memory");
        asm volatile("mbarrier.arrive.expect_tx.shared.b64 _, [%0], 512;" :: "r"(bar_s) : "memory");
        asm volatile("mbarrier.arrive.expect_tx.shared.b64 _, [%0], 512;" :: "r"(bar_s + 8) : "memory");
    }
    __syncthreads();
    asm volatile("barrier.cluster.arrive.aligned;" ::: "memory");
    asm volatile("barrier.cluster.wait.aligned;" ::: "memory");

    const unsigned peer = rank ^ 1u;
    unsigned hb_peer, bar_peer;
    asm("mapa.shared::cluster.u32 %0, %1, %2;" : "=r"(hb_peer)  : "r"(hb_s),  "r"(peer));
    asm("mapa.shared::cluster.u32 %0, %1, %2;" : "=r"(bar_peer) : "r"(bar_s), "r"(peer));

    const float bhv = fin ? __ldg(&bh[cg_f]) : 0.0f;
    const size_t xbase = ((size_t)b * Tsz) * Hsz + cg_f;

    // xp: 4-step-ahead register prefetch (finalizer lanes only)
    float xc[4] = {0, 0, 0, 0};
    if (fin) {
#pragma unroll
        for (int i = 0; i < 4; ++i) xc[i] = __ldg(&g_xp[xbase + (size_t)i * Hsz]);
    }

    unsigned ph0 = 0, ph1 = 0;

    for (int t0 = 0; t0 < Tsz; t0 += 4) {
        float xn[4] = {0, 0, 0, 0};
        if (fin && t0 + 4 < Tsz) {
#pragma unroll
            for (int i = 0; i < 4; ++i)
                xn[i] = __ldg(&g_xp[xbase + (size_t)(t0 + 4 + i) * Hsz]);
        }
#pragma unroll
        for (int u = 0; u < 4; ++u) {
            const int t  = t0 + u;
            const int p  = u & 1;
            const int np = p ^ 1;

            unsigned long long acc[8];
#pragma unroll
            for (int c = 0; c < 8; ++c) acc[c] = 0ULL;

            // local-half MAC: own CTA's h, visible since last bar.sync
            {
                ulonglong2 hv = *(const ulonglong2*)&hbuf[p][kl];
#pragma unroll
                for (int c = 0; c < 8; ++c) {
                    fma2(acc[c], hv.x, wl[c][0]);
                    fma2(acc[c], hv.y, wl[c][1]);
                }
            }

            // ONLY warp 0 polls the mbar; others park on bar.sync which
            // cannot release until warp 0 (post-wait) arrives.
            if (t > 0) {
                if (warp == 0) {
                    const unsigned bs = bar_s + (unsigned)p * 8u;
                    if (p) { mbar_wait_parity(bs, ph1); ph1 ^= 1u; }
                    else   { mbar_wait_parity(bs, ph0); ph0 ^= 1u; }
                    if (tid == 0)
                        asm volatile("mbarrier.arrive.expect_tx.shared.b64 _, [%0], 512;"
                                     :: "r"(bs) : "memory");
                }
            }
            __syncthreads();   // peer's half of hbuf[p] now visible to all

            // remote-half MAC
            {
                ulonglong2 hv = *(const ulonglong2*)&hbuf[p][kr];
#pragma unroll
                for (int c = 0; c < 8; ++c) {
                    fma2(acc[c], hv.x, wr[c][0]);
                    fma2(acc[c], hv.y, wr[c][1]);
                }
            }

            // scalarize: s[j] = partial for column cg_base + (j ^ m)
            float s[8];
#pragma unroll
            for (int c = 0; c < 8; ++c) {
                float2 v = unpack2(acc[c]);
                s[c] = v.x + v.y;
            }

            // SELECT-FREE butterfly: col(slot j) = j ^ m, so the value
            // received from lane^16 at slot j^4 is the same column.
            float t4[4];
#pragma unroll
            for (int j = 0; j < 4; ++j)
                t4[j] = s[j] + __shfl_xor_sync(0xFFFFFFFFu, s[j + 4], 16);
            float t2[2];
#pragma unroll
            for (int j = 0; j < 2; ++j)
                t2[j] = t4[j] + __shfl_xor_sync(0xFFFFFFFFu, t4[j + 2], 8);
            float sum = t2[0] + __shfl_xor_sync(0xFFFFFFFFu, t2[1], 4);
            sum += __shfl_xor_sync(0xFFFFFFFFu, sum, 2);
            sum += __shfl_xor_sync(0xFFFFFFFFu, sum, 1);
            // every lane now holds the total for column cg_base + m

            if (fin) {
                const float hn = tanh_fast(sum + xc[u] + bhv);
                hbuf[np][cg_f] = hn;                    // own half of h(t+1)
                out[xbase + (size_t)t * Hsz] = hn;
            }
            __syncthreads();   // own half of buf np fully stored & visible

            if (tid == 0 && t + 1 < Tsz) {
                asm volatile("fence.proxy.async.shared::cta;" ::: "memory");
                const unsigned off = (unsigned)np * 1024u + (unsigned)rank * 512u;
                asm volatile(
                    "cp.async.bulk.shared::cluster.shared::cta.mbarrier::complete_tx::bytes "
                    "[%0], [%1], %2, [%3];"
                    :: "r"(hb_peer + off), "r"(hb_s + off), "r"(512u),
                       "r"(bar_peer + (unsigned)np * 8u)
                    : "memory");
            }
        }
        if (fin) {
#pragma unroll
            for (int i = 0; i < 4; ++i) xc[i] = xn[i];
        }
    }

    asm volatile("barrier.cluster.arrive.aligned;" ::: "memory");
    asm volatile("barrier.cluster.wait.aligned;" ::: "memory");
}

// =====================================================================
extern "C" void kernel_launch(void* const* d_in, const int* in_sizes, int n_in,
                              void* d_out, int out_size)
{
    const float* x  = (const float*)d_in[0];  // [64, 4096, 128]
    const float* Wx = (const float*)d_in[1];  // [128, 256]
    const float* bx = (const float*)d_in[2];  // [256]
    const float* Wh = (const float*)d_in[3];  // [256, 256]
    const float* bh = (const float*)d_in[4];  // [256]
    float* out = (float*)d_out;               // [64, 4096, 256]

    const int smem_bytes = (128 * 128 + 128 * 64) * 4;  // 96 KB
    cudaFuncSetAttribute(xp_gemm_kernel,
                         cudaFuncAttributeMaxDynamicSharedMemorySize, smem_bytes);

    dim3 ggrid((Bsz * Tsz) / 128, Hsz / 64, 1);
    xp_gemm_kernel<<<ggrid, 256, smem_bytes>>>(x, Wx, bx);

    rnn_kernel<<<2 * Bsz, 512>>>(Wh, bh, out);
}